// round 7
// baseline (speedup 1.0000x reference)
#include <cuda_runtime.h>
#include <cuda_fp16.h>
#include <cstdint>

// Problem constants
#define N_  8192
#define M_  8192
#define D_  64
#define H_  32
#define T_  8

#define MSPLIT 4
#define TTM    256                      // X rows per CTA
#define TTN    128                      // Y rows per tile iter
#define TILES  ((M_ / MSPLIT) / TTN)    // 16
#define THREADS 512
#define LOG2E     1.4426950408889634f
#define HALF_L2E  0.7213475204444817f

typedef unsigned long long u64;
typedef unsigned int u32;

// ---------------- global scratch ----------------
__device__ __half g_Fhi[(N_ + M_) * H_];   // X rows pre-scaled by log2e; Y rows raw
__device__ __half g_Flo[(N_ + M_) * H_];
__device__ float  g_Fn[N_ + M_];           // -0.5*log2e*||f||^2
__device__ __half g_Vhi[M_ * T_];          // Yt hi, [j][t]
__device__ __half g_Vlo[M_ * T_];
__device__ float  g_part[(size_t)N_ * MSPLIT * (T_ + 1)];

// ---------------- helpers ----------------
__device__ __forceinline__ u32 smem_u32(const void* p) {
    u32 a; asm("{ .reg .u64 t; cvta.to.shared.u64 t, %1; cvt.u32.u64 %0, t; }" : "=r"(a) : "l"(p));
    return a;
}
__device__ __forceinline__ float ex2f(float x) {
    float r; asm("ex2.approx.ftz.f32 %0, %1;" : "=f"(r) : "f"(x)); return r;
}
__device__ __forceinline__ void ldmx4(u32& r0, u32& r1, u32& r2, u32& r3, u32 addr) {
    asm volatile("ldmatrix.sync.aligned.m8n8.x4.shared.b16 {%0,%1,%2,%3}, [%4];"
        : "=r"(r0), "=r"(r1), "=r"(r2), "=r"(r3) : "r"(addr));
}
__device__ __forceinline__ void ldmx2t(u32& r0, u32& r1, u32 addr) {
    asm volatile("ldmatrix.sync.aligned.m8n8.x2.trans.shared.b16 {%0,%1}, [%2];"
        : "=r"(r0), "=r"(r1) : "r"(addr));
}
__device__ __forceinline__ void mma16816(float& c0, float& c1, float& c2, float& c3,
                                         u32 a0, u32 a1, u32 a2, u32 a3, u32 b0, u32 b1) {
    asm volatile("mma.sync.aligned.m16n8k16.row.col.f32.f16.f16.f32 "
        "{%0,%1,%2,%3},{%4,%5,%6,%7},{%8,%9},{%0,%1,%2,%3};"
        : "+f"(c0), "+f"(c1), "+f"(c2), "+f"(c3)
        : "r"(a0), "r"(a1), "r"(a2), "r"(a3), "r"(b0), "r"(b1));
}

// ---------------- SMEM layout ----------------
#define PITCH   80                      // 64B data + 16B pad -> conflict-free ldmatrix
#define S_AHI   0                       // 256 rows * 80B
#define S_ALO   20480
#define S_B     40960                   // [stage][hi/lo]: stage*20480, lo +10240
#define S_V     81920                   // [stage][hi/lo]: stage*4096, lo +2048
#define S_CY    90112                   // [stage] 512B
#define SMEM_TOTAL 91136

// ---------------- kernel 1: MLP (4 rows per warp) + fused V prep ----------------
#define MLPBLKS ((N_ + M_) / 32)
__global__ __launch_bounds__(256)
void mlp_kernel(const float* __restrict__ X, const float* __restrict__ Y,
                const float* __restrict__ Yt,
                const float* __restrict__ W1, const float* __restrict__ b1,
                const float* __restrict__ W2, const float* __restrict__ b2,
                const float* __restrict__ W3, const float* __restrict__ b3)
{
    if (blockIdx.x >= MLPBLKS) {           // tail blocks: build V hi/lo
        int idx = (blockIdx.x - MLPBLKS) * 256 + threadIdx.x;  // M_*T_
        float v = Yt[idx];
        __half hi = __float2half_rn(v);
        g_Vhi[idx] = hi;
        g_Vlo[idx] = __float2half_rn(v - __half2float(hi));
        return;
    }

    __shared__ float sW1[D_ * H_], sW2[H_ * H_], sW3[H_ * H_];
    __shared__ float sb1[H_], sb2[H_], sb3[H_];
    int tid = threadIdx.x, w = tid >> 5, l = tid & 31;
    for (int i = tid; i < D_ * H_; i += 256) sW1[i] = W1[i];
    for (int i = tid; i < H_ * H_; i += 256) { sW2[i] = W2[i]; sW3[i] = W3[i]; }
    if (tid < H_) { sb1[tid] = b1[tid]; sb2[tid] = b2[tid]; sb3[tid] = b3[tid]; }
    __syncthreads();

    int row0 = blockIdx.x * 32 + w * 4;    // 4 rows per warp
    float x0[4], x1[4];
#pragma unroll
    for (int r = 0; r < 4; r++) {
        int row = row0 + r;
        const float* src = (row < N_) ? (X + (size_t)row * D_) : (Y + (size_t)(row - N_) * D_);
        x0[r] = src[l]; x1[r] = src[32 + l];
    }

    float h[4];
#pragma unroll
    for (int r = 0; r < 4; r++) h[r] = sb1[l];
#pragma unroll
    for (int k = 0; k < 32; k++) {
        float wv = sW1[k * 32 + l];
#pragma unroll
        for (int r = 0; r < 4; r++) h[r] = fmaf(__shfl_sync(0xffffffffu, x0[r], k), wv, h[r]);
    }
#pragma unroll
    for (int k = 0; k < 32; k++) {
        float wv = sW1[(32 + k) * 32 + l];
#pragma unroll
        for (int r = 0; r < 4; r++) h[r] = fmaf(__shfl_sync(0xffffffffu, x1[r], k), wv, h[r]);
    }
#pragma unroll
    for (int r = 0; r < 4; r++) h[r] = fmaxf(h[r], 0.f);

    float h2[4];
#pragma unroll
    for (int r = 0; r < 4; r++) h2[r] = sb2[l];
#pragma unroll
    for (int k = 0; k < 32; k++) {
        float wv = sW2[k * 32 + l];
#pragma unroll
        for (int r = 0; r < 4; r++) h2[r] = fmaf(__shfl_sync(0xffffffffu, h[r], k), wv, h2[r]);
    }
#pragma unroll
    for (int r = 0; r < 4; r++) h2[r] = fmaxf(h2[r], 0.f);

    float h3[4];
#pragma unroll
    for (int r = 0; r < 4; r++) h3[r] = sb3[l];
#pragma unroll
    for (int k = 0; k < 32; k++) {
        float wv = sW3[k * 32 + l];
#pragma unroll
        for (int r = 0; r < 4; r++) h3[r] = fmaf(__shfl_sync(0xffffffffu, h2[r], k), wv, h3[r]);
    }

#pragma unroll
    for (int r = 0; r < 4; r++) {
        int row = row0 + r;
        float v = fmaxf(h3[r], 0.f);
        float nx = v * v;
#pragma unroll
        for (int o = 16; o > 0; o >>= 1) nx += __shfl_xor_sync(0xffffffffu, nx, o);
        float vs = (row < N_) ? v * LOG2E : v;
        __half hi = __float2half_rn(vs);
        g_Fhi[(size_t)row * H_ + l] = hi;
        g_Flo[(size_t)row * H_ + l] = __float2half_rn(vs - __half2float(hi));
        if (l == 0) g_Fn[row] = -HALF_L2E * nx;
    }
}

// ---------------- kernel 2: HMMA flash kernel (512 thr, 256 rows/CTA) ----------------
__global__ __launch_bounds__(THREADS)
void dist_kernel()
{
    extern __shared__ char smem[];
    u32 sb = smem_u32(smem);
    int tid = threadIdx.x, w = tid >> 5, l = tid & 31;
    int g = l >> 2, tig = l & 3;
    int row0 = blockIdx.x * TTM;
    int m0   = blockIdx.y * (M_ / MSPLIT);

    // ---- preamble: A tile (2 chunks/thread) + tile0 of B/V/cy
    {
#pragma unroll
        for (int q = 0; q < 2; q++) {
            int id = tid + q * THREADS, r = id >> 2, c = id & 3;
            *(uint4*)(smem + S_AHI + r * PITCH + c * 16) = *(const uint4*)(g_Fhi + (size_t)(row0 + r) * H_ + c * 8);
            *(uint4*)(smem + S_ALO + r * PITCH + c * 16) = *(const uint4*)(g_Flo + (size_t)(row0 + r) * H_ + c * 8);
        }
        { int r = tid >> 2, c = tid & 3;
          *(uint4*)(smem + S_B + r * PITCH + c * 16)         = *(const uint4*)(g_Fhi + (size_t)(N_ + m0 + r) * H_ + c * 8);
          *(uint4*)(smem + S_B + 10240 + r * PITCH + c * 16) = *(const uint4*)(g_Flo + (size_t)(N_ + m0 + r) * H_ + c * 8); }
        if (tid < 128)      *(uint4*)(smem + S_V + tid * 16)            = *(const uint4*)(g_Vhi + (size_t)(m0 + tid) * T_);
        else if (tid < 256) *(uint4*)(smem + S_V + 2048 + (tid-128)*16) = *(const uint4*)(g_Vlo + (size_t)(m0 + tid - 128) * T_);
        else if (tid < 384) ((float*)(smem + S_CY))[tid - 256] = g_Fn[N_ + m0 + tid - 256];
    }
    __syncthreads();

    // ---- persistent A fragments
    u32 aH0[4], aH1[4], aL0[4], aL1[4];
    {
        u32 arow = (u32)(w * 16 + (l & 15)) * PITCH + (u32)(l >> 4) * 16;
        ldmx4(aH0[0], aH0[1], aH0[2], aH0[3], sb + S_AHI + arow);
        ldmx4(aH1[0], aH1[1], aH1[2], aH1[3], sb + S_AHI + arow + 32);
        ldmx4(aL0[0], aL0[1], aL0[2], aL0[3], sb + S_ALO + arow);
        ldmx4(aL1[0], aL1[1], aL1[2], aL1[3], sb + S_ALO + arow + 32);
    }

    float cx0 = g_Fn[row0 + w * 16 + g];
    float cx1 = g_Fn[row0 + w * 16 + g + 8];

    float oA0 = 0.f, oA1 = 0.f, oA2 = 0.f, oA3 = 0.f;   // P@Vhi chain
    float oB0 = 0.f, oB1 = 0.f, oB2 = 0.f, oB3 = 0.f;   // P@Vlo chain
    float s0 = 0.f, s1 = 0.f;

    u32 bArow = (u32)(l & 7) * PITCH + (u32)(l >> 3) * 16;
    u32 vArow = (u32)(l & 15) * 16;

#pragma unroll 1
    for (int i = 0; i < TILES; i++) {
        uint4 nbh, nbl, nv; float ncy = 0.f;
        bool pf = (i + 1 < TILES);
        if (pf) {
            int mb = m0 + (i + 1) * TTN;
            { int r = tid >> 2, c = tid & 3;
              nbh = *(const uint4*)(g_Fhi + (size_t)(N_ + mb + r) * H_ + c * 8);
              nbl = *(const uint4*)(g_Flo + (size_t)(N_ + mb + r) * H_ + c * 8); }
            if (tid < 128)      nv  = *(const uint4*)(g_Vhi + (size_t)(mb + tid) * T_);
            else if (tid < 256) nv  = *(const uint4*)(g_Vlo + (size_t)(mb + tid - 128) * T_);
            else if (tid < 384) ncy = g_Fn[N_ + mb + tid - 256];
        }

        int ib = i & 1;
        u32 Bhi = sb + S_B + ib * 20480, Blo = Bhi + 10240;
        u32 Vhi = sb + S_V + ib * 4096,  Vlo = Vhi + 2048;
        const float* cyb = (const float*)(smem + S_CY + ib * 512);

#pragma unroll 1
        for (int s = 0; s < 8; s++) {
            u32 aP[4];
#pragma unroll
            for (int hhalf = 0; hhalf < 2; hhalf++) {
                int nc = 2 * s + hhalf;
                u32 bh[4], bl[4];
                ldmx4(bh[0], bh[1], bh[2], bh[3], Bhi + (u32)nc * (8 * PITCH) + bArow);
                ldmx4(bl[0], bl[1], bl[2], bl[3], Blo + (u32)nc * (8 * PITCH) + bArow);

                // 3 independent 2-MMA chains
                float cA0 = 0.f, cA1 = 0.f, cA2 = 0.f, cA3 = 0.f;
                float cB0 = 0.f, cB1 = 0.f, cB2 = 0.f, cB3 = 0.f;
                float cC0 = 0.f, cC1 = 0.f, cC2 = 0.f, cC3 = 0.f;
                mma16816(cA0, cA1, cA2, cA3, aH0[0], aH0[1], aH0[2], aH0[3], bh[0], bh[1]);
                mma16816(cB0, cB1, cB2, cB3, aH0[0], aH0[1], aH0[2], aH0[3], bl[0], bl[1]);
                mma16816(cC0, cC1, cC2, cC3, aL0[0], aL0[1], aL0[2], aL0[3], bh[0], bh[1]);
                mma16816(cA0, cA1, cA2, cA3, aH1[0], aH1[1], aH1[2], aH1[3], bh[2], bh[3]);
                mma16816(cB0, cB1, cB2, cB3, aH1[0], aH1[1], aH1[2], aH1[3], bl[2], bl[3]);
                mma16816(cC0, cC1, cC2, cC3, aL1[0], aL1[1], aL1[2], aL1[3], bh[2], bh[3]);
                float c0 = cA0 + cB0 + cC0, c1 = cA1 + cB1 + cC1;
                float c2 = cA2 + cB2 + cC2, c3 = cA3 + cB3 + cC3;

                float2 cy = *(const float2*)(cyb + nc * 8 + 2 * tig);
                float k0 = ex2f(fminf(c0 + (cx0 + cy.x), 0.f));
                float k1 = ex2f(fminf(c1 + (cx0 + cy.y), 0.f));
                float k2 = ex2f(fminf(c2 + (cx1 + cy.x), 0.f));
                float k3 = ex2f(fminf(c3 + (cx1 + cy.y), 0.f));
                s0 += k0 + k1;
                s1 += k2 + k3;

                __half2 h01 = __floats2half2_rn(k0, k1);
                __half2 h23 = __floats2half2_rn(k2, k3);
                aP[2 * hhalf]     = *(u32*)&h01;
                aP[2 * hhalf + 1] = *(u32*)&h23;
            }

            u32 vh[2], vl[2];
            ldmx2t(vh[0], vh[1], Vhi + (u32)s * 256 + vArow);
            ldmx2t(vl[0], vl[1], Vlo + (u32)s * 256 + vArow);
            mma16816(oA0, oA1, oA2, oA3, aP[0], aP[1], aP[2], aP[3], vh[0], vh[1]);
            mma16816(oB0, oB1, oB2, oB3, aP[0], aP[1], aP[2], aP[3], vl[0], vl[1]);
        }

        if (pf) {
            int ib2 = (i + 1) & 1;
            { int r = tid >> 2, c = tid & 3;
              *(uint4*)(smem + S_B + ib2 * 20480 + r * PITCH + c * 16)         = nbh;
              *(uint4*)(smem + S_B + ib2 * 20480 + 10240 + r * PITCH + c * 16) = nbl; }
            if (tid < 128)      *(uint4*)(smem + S_V + ib2 * 4096 + tid * 16)              = nv;
            else if (tid < 256) *(uint4*)(smem + S_V + ib2 * 4096 + 2048 + (tid-128) * 16) = nv;
            else if (tid < 384) ((float*)(smem + S_CY + ib2 * 512))[tid - 256] = ncy;
        }
        __syncthreads();
    }

    float o0 = oA0 + oB0, o1 = oA1 + oB1, o2 = oA2 + oB2, o3 = oA3 + oB3;

    s0 += __shfl_xor_sync(0xffffffffu, s0, 1);
    s0 += __shfl_xor_sync(0xffffffffu, s0, 2);
    s1 += __shfl_xor_sync(0xffffffffu, s1, 1);
    s1 += __shfl_xor_sync(0xffffffffu, s1, 2);

    int ra = row0 + w * 16 + g;
    float* pa = g_part + ((size_t)ra * MSPLIT + blockIdx.y) * (T_ + 1);
    float* pb = g_part + ((size_t)(ra + 8) * MSPLIT + blockIdx.y) * (T_ + 1);
    pa[2 * tig] = o0; pa[2 * tig + 1] = o1;
    pb[2 * tig] = o2; pb[2 * tig + 1] = o3;
    if (tig == 0) { pa[T_] = s0; pb[T_] = s1; }
}

// ---------------- kernel 3: combine partials, normalize (thread per row*t) ----------------
__global__ __launch_bounds__(256)
void reduce_kernel(float* __restrict__ out)
{
    int idx = blockIdx.x * 256 + threadIdx.x;   // N_*T_
    int row = idx >> 3, t = idx & 7;
    const float* p = g_part + (size_t)row * MSPLIT * (T_ + 1);
    float st = 0.f, sk = 0.f;
#pragma unroll
    for (int c = 0; c < MSPLIT; c++) {
        st += p[c * (T_ + 1) + t];
        sk += p[c * (T_ + 1) + T_];
    }
    out[idx] = st / sk;
}

// ---------------- launch ----------------
extern "C" void kernel_launch(void* const* d_in, const int* in_sizes, int n_in,
                              void* d_out, int out_size)
{
    (void)in_sizes; (void)n_in; (void)out_size;
    const float* X  = (const float*)d_in[0];
    const float* Y  = (const float*)d_in[1];
    const float* Yt = (const float*)d_in[2];
    const float* W1 = (const float*)d_in[3];
    const float* b1 = (const float*)d_in[4];
    const float* W2 = (const float*)d_in[5];
    const float* b2 = (const float*)d_in[6];
    const float* W3 = (const float*)d_in[7];
    const float* b3 = (const float*)d_in[8];
    float* out = (float*)d_out;

    cudaFuncSetAttribute(dist_kernel, cudaFuncAttributeMaxDynamicSharedMemorySize, SMEM_TOTAL);

    mlp_kernel<<<MLPBLKS + (M_ * T_) / 256, 256>>>(X, Y, Yt, W1, b1, W2, b2, W3, b3);
    dist_kernel<<<dim3(N_ / TTM, MSPLIT), THREADS, SMEM_TOTAL>>>();
    reduce_kernel<<<(N_ * T_) / 256, 256>>>(out);
}

// round 9
// speedup vs baseline: 1.4574x; 1.4574x over previous
#include <cuda_runtime.h>
#include <cuda_fp16.h>
#include <cstdint>

// Problem constants
#define N_  8192
#define M_  8192
#define D_  64
#define H_  32
#define T_  8

#define MSPLIT 4
#define TTM    256                      // X rows per CTA
#define TTN    128                      // Y rows per tile iter
#define TILES  ((M_ / MSPLIT) / TTN)    // 16
#define THREADS 512
#define LOG2E     1.4426950408889634f
#define HALF_L2E  0.7213475204444817f

typedef unsigned long long u64;
typedef unsigned int u32;

// ---------------- global scratch ----------------
__device__ __half g_Fhi[(N_ + M_) * H_];   // X rows pre-scaled by log2e; Y rows raw
__device__ __half g_Flo[(N_ + M_) * H_];
__device__ float  g_Fn[N_ + M_];           // -0.5*log2e*||f||^2
__device__ __half g_Vhi[M_ * T_];          // Yt hi, [j][t]
__device__ __half g_Vlo[M_ * T_];
// partials transposed for coalesced reduce: [chunk][t(0..8)][row]
__device__ float  g_part[MSPLIT * (T_ + 1) * N_];
#define IDXP(c, t, row) ((((c) * (T_ + 1)) + (t)) * N_ + (row))

// ---------------- helpers ----------------
__device__ __forceinline__ u32 smem_u32(const void* p) {
    u32 a; asm("{ .reg .u64 t; cvta.to.shared.u64 t, %1; cvt.u32.u64 %0, t; }" : "=r"(a) : "l"(p));
    return a;
}
__device__ __forceinline__ float ex2f(float x) {
    float r; asm("ex2.approx.ftz.f32 %0, %1;" : "=f"(r) : "f"(x)); return r;
}
__device__ __forceinline__ void ldmx4(u32& r0, u32& r1, u32& r2, u32& r3, u32 addr) {
    asm volatile("ldmatrix.sync.aligned.m8n8.x4.shared.b16 {%0,%1,%2,%3}, [%4];"
        : "=r"(r0), "=r"(r1), "=r"(r2), "=r"(r3) : "r"(addr));
}
__device__ __forceinline__ void ldmx2t(u32& r0, u32& r1, u32 addr) {
    asm volatile("ldmatrix.sync.aligned.m8n8.x2.trans.shared.b16 {%0,%1}, [%2];"
        : "=r"(r0), "=r"(r1) : "r"(addr));
}
__device__ __forceinline__ void mma16816(float& c0, float& c1, float& c2, float& c3,
                                         u32 a0, u32 a1, u32 a2, u32 a3, u32 b0, u32 b1) {
    asm volatile("mma.sync.aligned.m16n8k16.row.col.f32.f16.f16.f32 "
        "{%0,%1,%2,%3},{%4,%5,%6,%7},{%8,%9},{%0,%1,%2,%3};"
        : "+f"(c0), "+f"(c1), "+f"(c2), "+f"(c3)
        : "r"(a0), "r"(a1), "r"(a2), "r"(a3), "r"(b0), "r"(b1));
}

// ---------------- SMEM layout ----------------
#define PITCH   80                      // 64B data + 16B pad -> conflict-free ldmatrix
#define S_AHI   0                       // 256 rows * 80B
#define S_ALO   20480
#define S_B     40960                   // [stage][hi/lo]: stage*20480, lo +10240
#define S_V     81920                   // [stage][hi/lo]: stage*4096, lo +2048
#define S_CY    90112                   // [stage] 512B
#define SMEM_TOTAL 91136

// ---------------- kernel 1: MLP (2 rows/warp, split chains) + fused V prep ----------------
#define MLPBLKS ((N_ + M_) / 16)
__global__ __launch_bounds__(256)
void mlp_kernel(const float* __restrict__ X, const float* __restrict__ Y,
                const float* __restrict__ Yt,
                const float* __restrict__ W1, const float* __restrict__ b1,
                const float* __restrict__ W2, const float* __restrict__ b2,
                const float* __restrict__ W3, const float* __restrict__ b3)
{
    if (blockIdx.x >= MLPBLKS) {           // tail blocks: build V hi/lo
        int idx = (blockIdx.x - MLPBLKS) * 256 + threadIdx.x;  // M_*T_
        float v = Yt[idx];
        __half hi = __float2half_rn(v);
        g_Vhi[idx] = hi;
        g_Vlo[idx] = __float2half_rn(v - __half2float(hi));
        return;
    }

    __shared__ float sW1[D_ * H_], sW2[H_ * H_], sW3[H_ * H_];
    __shared__ float sb1[H_], sb2[H_], sb3[H_];
    int tid = threadIdx.x, w = tid >> 5, l = tid & 31;
    for (int i = tid; i < D_ * H_; i += 256) sW1[i] = W1[i];
    for (int i = tid; i < H_ * H_; i += 256) { sW2[i] = W2[i]; sW3[i] = W3[i]; }
    if (tid < H_) { sb1[tid] = b1[tid]; sb2[tid] = b2[tid]; sb3[tid] = b3[tid]; }
    __syncthreads();

    int row0 = blockIdx.x * 16 + w * 2;    // 2 rows per warp
    float x0[2], x1[2];
#pragma unroll
    for (int r = 0; r < 2; r++) {
        int row = row0 + r;
        const float* src = (row < N_) ? (X + (size_t)row * D_) : (Y + (size_t)(row - N_) * D_);
        x0[r] = src[l]; x1[r] = src[32 + l];
    }

    // layer 1: two 32-long chains per row (x0-half, x1-half)
    float ha[2] = { sb1[l], sb1[l] }, hb[2] = { 0.f, 0.f };
#pragma unroll
    for (int k = 0; k < 32; k++) {
        float wa = sW1[k * 32 + l];
        float wb = sW1[(32 + k) * 32 + l];
#pragma unroll
        for (int r = 0; r < 2; r++) {
            ha[r] = fmaf(__shfl_sync(0xffffffffu, x0[r], k), wa, ha[r]);
            hb[r] = fmaf(__shfl_sync(0xffffffffu, x1[r], k), wb, hb[r]);
        }
    }
    float h[2];
#pragma unroll
    for (int r = 0; r < 2; r++) h[r] = fmaxf(ha[r] + hb[r], 0.f);

    // layer 2: split k into two 16-long chains
    float h2a[2] = { sb2[l], sb2[l] }, h2b[2] = { 0.f, 0.f };
#pragma unroll
    for (int k = 0; k < 16; k++) {
        float wa = sW2[k * 32 + l];
        float wb = sW2[(16 + k) * 32 + l];
#pragma unroll
        for (int r = 0; r < 2; r++) {
            h2a[r] = fmaf(__shfl_sync(0xffffffffu, h[r], k), wa, h2a[r]);
            h2b[r] = fmaf(__shfl_sync(0xffffffffu, h[r], 16 + k), wb, h2b[r]);
        }
    }
    float h2[2];
#pragma unroll
    for (int r = 0; r < 2; r++) h2[r] = fmaxf(h2a[r] + h2b[r], 0.f);

    // layer 3
    float h3a[2] = { sb3[l], sb3[l] }, h3b[2] = { 0.f, 0.f };
#pragma unroll
    for (int k = 0; k < 16; k++) {
        float wa = sW3[k * 32 + l];
        float wb = sW3[(16 + k) * 32 + l];
#pragma unroll
        for (int r = 0; r < 2; r++) {
            h3a[r] = fmaf(__shfl_sync(0xffffffffu, h2[r], k), wa, h3a[r]);
            h3b[r] = fmaf(__shfl_sync(0xffffffffu, h2[r], 16 + k), wb, h3b[r]);
        }
    }

#pragma unroll
    for (int r = 0; r < 2; r++) {
        int row = row0 + r;
        float v = fmaxf(h3a[r] + h3b[r], 0.f);
        float nx = v * v;
#pragma unroll
        for (int o = 16; o > 0; o >>= 1) nx += __shfl_xor_sync(0xffffffffu, nx, o);
        float vs = (row < N_) ? v * LOG2E : v;
        __half hi = __float2half_rn(vs);
        g_Fhi[(size_t)row * H_ + l] = hi;
        g_Flo[(size_t)row * H_ + l] = __float2half_rn(vs - __half2float(hi));
        if (l == 0) g_Fn[row] = -HALF_L2E * nx;
    }
}

// ---------------- kernel 2: HMMA flash kernel (512 thr, 256 rows/CTA) ----------------
__global__ __launch_bounds__(THREADS)
void dist_kernel()
{
    extern __shared__ char smem[];
    u32 sb = smem_u32(smem);
    int tid = threadIdx.x, w = tid >> 5, l = tid & 31;
    int g = l >> 2, tig = l & 3;
    int row0 = blockIdx.x * TTM;
    int m0   = blockIdx.y * (M_ / MSPLIT);

    // ---- preamble: A tile (2 chunks/thread) + tile0 of B/V/cy
    {
#pragma unroll
        for (int q = 0; q < 2; q++) {
            int id = tid + q * THREADS, r = id >> 2, c = id & 3;
            *(uint4*)(smem + S_AHI + r * PITCH + c * 16) = *(const uint4*)(g_Fhi + (size_t)(row0 + r) * H_ + c * 8);
            *(uint4*)(smem + S_ALO + r * PITCH + c * 16) = *(const uint4*)(g_Flo + (size_t)(row0 + r) * H_ + c * 8);
        }
        { int r = tid >> 2, c = tid & 3;
          *(uint4*)(smem + S_B + r * PITCH + c * 16)         = *(const uint4*)(g_Fhi + (size_t)(N_ + m0 + r) * H_ + c * 8);
          *(uint4*)(smem + S_B + 10240 + r * PITCH + c * 16) = *(const uint4*)(g_Flo + (size_t)(N_ + m0 + r) * H_ + c * 8); }
        if (tid < 128)      *(uint4*)(smem + S_V + tid * 16)            = *(const uint4*)(g_Vhi + (size_t)(m0 + tid) * T_);
        else if (tid < 256) *(uint4*)(smem + S_V + 2048 + (tid-128)*16) = *(const uint4*)(g_Vlo + (size_t)(m0 + tid - 128) * T_);
        else if (tid < 384) ((float*)(smem + S_CY))[tid - 256] = g_Fn[N_ + m0 + tid - 256];
    }
    __syncthreads();

    // ---- persistent A fragments
    u32 aH0[4], aH1[4], aL0[4], aL1[4];
    {
        u32 arow = (u32)(w * 16 + (l & 15)) * PITCH + (u32)(l >> 4) * 16;
        ldmx4(aH0[0], aH0[1], aH0[2], aH0[3], sb + S_AHI + arow);
        ldmx4(aH1[0], aH1[1], aH1[2], aH1[3], sb + S_AHI + arow + 32);
        ldmx4(aL0[0], aL0[1], aL0[2], aL0[3], sb + S_ALO + arow);
        ldmx4(aL1[0], aL1[1], aL1[2], aL1[3], sb + S_ALO + arow + 32);
    }

    float cx0 = g_Fn[row0 + w * 16 + g];
    float cx1 = g_Fn[row0 + w * 16 + g + 8];

    float oA0 = 0.f, oA1 = 0.f, oA2 = 0.f, oA3 = 0.f;   // Phi@Vhi chain
    float oB0 = 0.f, oB1 = 0.f, oB2 = 0.f, oB3 = 0.f;   // correction chain
    float s0 = 0.f, s1 = 0.f;

    u32 bArow = (u32)(l & 7) * PITCH + (u32)(l >> 3) * 16;
    u32 vArow = (u32)(l & 15) * 16;

#pragma unroll 1
    for (int i = 0; i < TILES; i++) {
        uint4 nbh, nbl, nv; float ncy = 0.f;
        bool pf = (i + 1 < TILES);
        if (pf) {
            int mb = m0 + (i + 1) * TTN;
            { int r = tid >> 2, c = tid & 3;
              nbh = *(const uint4*)(g_Fhi + (size_t)(N_ + mb + r) * H_ + c * 8);
              nbl = *(const uint4*)(g_Flo + (size_t)(N_ + mb + r) * H_ + c * 8); }
            if (tid < 128)      nv  = *(const uint4*)(g_Vhi + (size_t)(mb + tid) * T_);
            else if (tid < 256) nv  = *(const uint4*)(g_Vlo + (size_t)(mb + tid - 128) * T_);
            else if (tid < 384) ncy = g_Fn[N_ + mb + tid - 256];
        }

        int ib = i & 1;
        u32 Bhi = sb + S_B + ib * 20480, Blo = Bhi + 10240;
        u32 Vhi = sb + S_V + ib * 4096,  Vlo = Vhi + 2048;
        const float* cyb = (const float*)(smem + S_CY + ib * 512);

#pragma unroll 1
        for (int s = 0; s < 8; s++) {
            u32 aP[4], aPl[4];
#pragma unroll
            for (int hhalf = 0; hhalf < 2; hhalf++) {
                int nc = 2 * s + hhalf;
                u32 bh[4], bl[4];
                ldmx4(bh[0], bh[1], bh[2], bh[3], Bhi + (u32)nc * (8 * PITCH) + bArow);
                ldmx4(bl[0], bl[1], bl[2], bl[3], Blo + (u32)nc * (8 * PITCH) + bArow);

                // 3 independent 2-MMA chains
                float cA0 = 0.f, cA1 = 0.f, cA2 = 0.f, cA3 = 0.f;
                float cB0 = 0.f, cB1 = 0.f, cB2 = 0.f, cB3 = 0.f;
                float cC0 = 0.f, cC1 = 0.f, cC2 = 0.f, cC3 = 0.f;
                mma16816(cA0, cA1, cA2, cA3, aH0[0], aH0[1], aH0[2], aH0[3], bh[0], bh[1]);
                mma16816(cB0, cB1, cB2, cB3, aH0[0], aH0[1], aH0[2], aH0[3], bl[0], bl[1]);
                mma16816(cC0, cC1, cC2, cC3, aL0[0], aL0[1], aL0[2], aL0[3], bh[0], bh[1]);
                mma16816(cA0, cA1, cA2, cA3, aH1[0], aH1[1], aH1[2], aH1[3], bh[2], bh[3]);
                mma16816(cB0, cB1, cB2, cB3, aH1[0], aH1[1], aH1[2], aH1[3], bl[2], bl[3]);
                mma16816(cC0, cC1, cC2, cC3, aL1[0], aL1[1], aL1[2], aL1[3], bh[2], bh[3]);
                float c0 = cA0 + cB0 + cC0, c1 = cA1 + cB1 + cC1;
                float c2 = cA2 + cB2 + cC2, c3 = cA3 + cB3 + cC3;

                float2 cy = *(const float2*)(cyb + nc * 8 + 2 * tig);
                float k0 = ex2f(fminf(c0 + (cx0 + cy.x), 0.f));
                float k1 = ex2f(fminf(c1 + (cx0 + cy.y), 0.f));
                float k2 = ex2f(fminf(c2 + (cx1 + cy.x), 0.f));
                float k3 = ex2f(fminf(c3 + (cx1 + cy.y), 0.f));
                s0 += k0 + k1;
                s1 += k2 + k3;

                __half2 h01 = __floats2half2_rn(k0, k1);
                __half2 h23 = __floats2half2_rn(k2, k3);
                float2 f01 = __half22float2(h01);
                float2 f23 = __half22float2(h23);
                __half2 l01 = __floats2half2_rn(k0 - f01.x, k1 - f01.y);
                __half2 l23 = __floats2half2_rn(k2 - f23.x, k3 - f23.y);
                aP [2 * hhalf]     = *(u32*)&h01;
                aP [2 * hhalf + 1] = *(u32*)&h23;
                aPl[2 * hhalf]     = *(u32*)&l01;
                aPl[2 * hhalf + 1] = *(u32*)&l23;
            }

            u32 vh[2], vl[2];
            ldmx2t(vh[0], vh[1], Vhi + (u32)s * 256 + vArow);
            ldmx2t(vl[0], vl[1], Vlo + (u32)s * 256 + vArow);
            mma16816(oA0, oA1, oA2, oA3, aP[0],  aP[1],  aP[2],  aP[3],  vh[0], vh[1]);
            mma16816(oB0, oB1, oB2, oB3, aPl[0], aPl[1], aPl[2], aPl[3], vh[0], vh[1]);
            mma16816(oB0, oB1, oB2, oB3, aP[0],  aP[1],  aP[2],  aP[3],  vl[0], vl[1]);
        }

        if (pf) {
            int ib2 = (i + 1) & 1;
            { int r = tid >> 2, c = tid & 3;
              *(uint4*)(smem + S_B + ib2 * 20480 + r * PITCH + c * 16)         = nbh;
              *(uint4*)(smem + S_B + ib2 * 20480 + 10240 + r * PITCH + c * 16) = nbl; }
            if (tid < 128)      *(uint4*)(smem + S_V + ib2 * 4096 + tid * 16)              = nv;
            else if (tid < 256) *(uint4*)(smem + S_V + ib2 * 4096 + 2048 + (tid-128) * 16) = nv;
            else if (tid < 384) ((float*)(smem + S_CY + ib2 * 512))[tid - 256] = ncy;
        }
        __syncthreads();
    }

    float o0 = oA0 + oB0, o1 = oA1 + oB1, o2 = oA2 + oB2, o3 = oA3 + oB3;

    s0 += __shfl_xor_sync(0xffffffffu, s0, 1);
    s0 += __shfl_xor_sync(0xffffffffu, s0, 2);
    s1 += __shfl_xor_sync(0xffffffffu, s1, 1);
    s1 += __shfl_xor_sync(0xffffffffu, s1, 2);

    int ra = row0 + w * 16 + g;
    int rb = ra + 8;
    int by = blockIdx.y;
    g_part[IDXP(by, 2 * tig,     ra)] = o0;
    g_part[IDXP(by, 2 * tig + 1, ra)] = o1;
    g_part[IDXP(by, 2 * tig,     rb)] = o2;
    g_part[IDXP(by, 2 * tig + 1, rb)] = o3;
    if (tig == 0) { g_part[IDXP(by, T_, ra)] = s0; g_part[IDXP(by, T_, rb)] = s1; }
}

// ---------------- kernel 3: combine partials, normalize (coalesced) ----------------
__global__ __launch_bounds__(256)
void reduce_kernel(float* __restrict__ out)
{
    int row = blockIdx.x * 256 + threadIdx.x;   // N_ rows
    float sk = 0.f;
#pragma unroll
    for (int c = 0; c < MSPLIT; c++) sk += g_part[IDXP(c, T_, row)];
    float inv = 1.f / sk;
    float o[T_];
#pragma unroll
    for (int t = 0; t < T_; t++) {
        float st = 0.f;
#pragma unroll
        for (int c = 0; c < MSPLIT; c++) st += g_part[IDXP(c, t, row)];
        o[t] = st * inv;
    }
    float4* dst = (float4*)(out + (size_t)row * T_);
    dst[0] = make_float4(o[0], o[1], o[2], o[3]);
    dst[1] = make_float4(o[4], o[5], o[6], o[7]);
}

// ---------------- launch ----------------
extern "C" void kernel_launch(void* const* d_in, const int* in_sizes, int n_in,
                              void* d_out, int out_size)
{
    (void)in_sizes; (void)n_in; (void)out_size;
    const float* X  = (const float*)d_in[0];
    const float* Y  = (const float*)d_in[1];
    const float* Yt = (const float*)d_in[2];
    const float* W1 = (const float*)d_in[3];
    const float* b1 = (const float*)d_in[4];
    const float* W2 = (const float*)d_in[5];
    const float* b2 = (const float*)d_in[6];
    const float* W3 = (const float*)d_in[7];
    const float* b3 = (const float*)d_in[8];
    float* out = (float*)d_out;

    cudaFuncSetAttribute(dist_kernel, cudaFuncAttributeMaxDynamicSharedMemorySize, SMEM_TOTAL);

    mlp_kernel<<<MLPBLKS + (M_ * T_) / 256, 256>>>(X, Y, Yt, W1, b1, W2, b2, W3, b3);
    dist_kernel<<<dim3(N_ / TTM, MSPLIT), THREADS, SMEM_TOTAL>>>();
    reduce_kernel<<<N_ / 256, 256>>>(out);
}

// round 11
// speedup vs baseline: 1.8291x; 1.2551x over previous
#include <cuda_runtime.h>
#include <cuda_fp16.h>
#include <cstdint>

// Problem constants
#define N_  8192
#define M_  8192
#define D_  64
#define H_  32
#define T_  8

#define MSPLIT 4
#define TTM    256                      // X rows per CTA (dist)
#define TTN    128                      // Y rows per tile iter
#define TILES  ((M_ / MSPLIT) / TTN)    // 16
#define THREADS 512
#define LOG2E     1.4426950408889634f
#define HALF_L2E  0.7213475204444817f

typedef unsigned long long u64;
typedef unsigned int u32;

// ---------------- global scratch ----------------
__device__ __half g_Fhi[(N_ + M_) * H_];   // X rows pre-scaled by log2e; Y rows raw
__device__ __half g_Flo[(N_ + M_) * H_];
__device__ float  g_Fn[N_ + M_];           // -0.5*log2e*||f||^2
__device__ __half g_Vhi[M_ * T_];          // Yt hi, [j][t]
__device__ __half g_Vlo[M_ * T_];
// partials transposed for coalesced reduce: [chunk][t(0..8)][row]
__device__ float  g_part[MSPLIT * (T_ + 1) * N_];
#define IDXP(c, t, row) ((((c) * (T_ + 1)) + (t)) * N_ + (row))

// ---------------- helpers ----------------
__device__ __forceinline__ u32 smem_u32(const void* p) {
    u32 a; asm("{ .reg .u64 t; cvta.to.shared.u64 t, %1; cvt.u32.u64 %0, t; }" : "=r"(a) : "l"(p));
    return a;
}
__device__ __forceinline__ float ex2f(float x) {
    float r; asm("ex2.approx.ftz.f32 %0, %1;" : "=f"(r) : "f"(x)); return r;
}
__device__ __forceinline__ void ldmx4(u32& r0, u32& r1, u32& r2, u32& r3, u32 addr) {
    asm volatile("ldmatrix.sync.aligned.m8n8.x4.shared.b16 {%0,%1,%2,%3}, [%4];"
        : "=r"(r0), "=r"(r1), "=r"(r2), "=r"(r3) : "r"(addr));
}
__device__ __forceinline__ void ldmx2t(u32& r0, u32& r1, u32 addr) {
    asm volatile("ldmatrix.sync.aligned.m8n8.x2.trans.shared.b16 {%0,%1}, [%2];"
        : "=r"(r0), "=r"(r1) : "r"(addr));
}
__device__ __forceinline__ void mma16816(float& c0, float& c1, float& c2, float& c3,
                                         u32 a0, u32 a1, u32 a2, u32 a3, u32 b0, u32 b1) {
    asm volatile("mma.sync.aligned.m16n8k16.row.col.f32.f16.f16.f32 "
        "{%0,%1,%2,%3},{%4,%5,%6,%7},{%8,%9},{%0,%1,%2,%3};"
        : "+f"(c0), "+f"(c1), "+f"(c2), "+f"(c3)
        : "r"(a0), "r"(a1), "r"(a2), "r"(a3), "r"(b0), "r"(b1));
}
__device__ __forceinline__ u32 packh2(float a, float b) {
    __half2 h = __floats2half2_rn(a, b);
    return *(u32*)&h;
}

// ---------------- dist SMEM layout ----------------
#define PITCH   80                      // 64B data + 16B pad -> conflict-free ldmatrix
#define S_AHI   0                       // 256 rows * 80B
#define S_ALO   20480
#define S_B     40960                   // [stage][hi/lo]: stage*20480, lo +10240
#define S_V     81920                   // [stage][hi/lo]: stage*4096, lo +2048
#define S_CY    90112                   // [stage] 512B
#define SMEM_TOTAL 91136

// ---------------- mlp2 SMEM layout (dynamic) ----------------
#define XP      144                     // X row pitch bytes (128B data + 16 pad)
#define M2_FH   0                       // 128*144 = 18432
#define M2_FL   18432
#define M2_WH   36864                   // 128 rows (W1:0-63, W2:64-95, W3:96-127) * 80B
#define M2_WL   47104
#define M2_BI   57344                   // 96 floats
#define M2_TOTAL 57728

// ---------------- kernel 1: MLP on tensor cores + fused V prep ----------------
#define MLP2BLKS ((N_ + M_) / 128)      // 128
__global__ __launch_bounds__(256)
void mlp2_kernel(const float* __restrict__ X, const float* __restrict__ Y,
                 const float* __restrict__ Yt,
                 const float* __restrict__ W1, const float* __restrict__ b1,
                 const float* __restrict__ W2, const float* __restrict__ b2,
                 const float* __restrict__ W3, const float* __restrict__ b3)
{
    if (blockIdx.x >= MLP2BLKS) {           // tail blocks: build V hi/lo
        int idx = (blockIdx.x - MLP2BLKS) * 256 + threadIdx.x;  // M_*T_
        float v = Yt[idx];
        __half hi = __float2half_rn(v);
        g_Vhi[idx] = hi;
        g_Vlo[idx] = __float2half_rn(v - __half2float(hi));
        return;
    }

    extern __shared__ char smem[];
    u32 sb = smem_u32(smem);
    int tid = threadIdx.x, w = tid >> 5, l = tid & 31;
    int g = l >> 2, tig = l & 3;
    int row0 = blockIdx.x * 128;
    bool isX = (row0 < N_);
    const float* src = isX ? (X + (size_t)row0 * D_) : (Y + (size_t)(row0 - N_) * D_);

    // ---- load X tile [128 x 64] f32 -> hi/lo f16, pitch 144B
#pragma unroll
    for (int q = 0; q < 8; q++) {
        int idx = q * 256 + tid;            // 2048 float4
        int r = idx >> 4, c4 = idx & 15;
        float4 v = ((const float4*)src)[idx];
        float hx = __half2float(__float2half_rn(v.x));
        float hy = __half2float(__float2half_rn(v.y));
        float hz = __half2float(__float2half_rn(v.z));
        float hw = __half2float(__float2half_rn(v.w));
        u32* ph = (u32*)(smem + M2_FH + r * XP + c4 * 8);
        u32* pl = (u32*)(smem + M2_FL + r * XP + c4 * 8);
        ph[0] = packh2(v.x, v.y);        ph[1] = packh2(v.z, v.w);
        pl[0] = packh2(v.x - hx, v.y - hy); pl[1] = packh2(v.z - hz, v.w - hw);
    }
    // ---- load weights [k][n] hi/lo, pitch 80B. W1 rows 0-63, W2 64-95, W3 96-127
#pragma unroll
    for (int q = 0; q < 2; q++) {           // W1: 512 float4
        int idx = q * 256 + tid;
        int r = idx >> 3, c4 = idx & 7;
        float4 v = ((const float4*)W1)[idx];
        float hx = __half2float(__float2half_rn(v.x));
        float hy = __half2float(__float2half_rn(v.y));
        float hz = __half2float(__float2half_rn(v.z));
        float hw = __half2float(__float2half_rn(v.w));
        u32* ph = (u32*)(smem + M2_WH + r * PITCH + c4 * 8);
        u32* pl = (u32*)(smem + M2_WL + r * PITCH + c4 * 8);
        ph[0] = packh2(v.x, v.y);        ph[1] = packh2(v.z, v.w);
        pl[0] = packh2(v.x - hx, v.y - hy); pl[1] = packh2(v.z - hz, v.w - hw);
    }
    {                                        // W2 + W3: 256+256 float4
        const float4* Wsrc[2] = { (const float4*)W2, (const float4*)W3 };
#pragma unroll
        for (int m = 0; m < 2; m++) {
            int r = 64 + m * 32 + (tid >> 3), c4 = tid & 7;
            float4 v = Wsrc[m][tid];
            float hx = __half2float(__float2half_rn(v.x));
            float hy = __half2float(__float2half_rn(v.y));
            float hz = __half2float(__float2half_rn(v.z));
            float hw = __half2float(__float2half_rn(v.w));
            u32* ph = (u32*)(smem + M2_WH + r * PITCH + c4 * 8);
            u32* pl = (u32*)(smem + M2_WL + r * PITCH + c4 * 8);
            ph[0] = packh2(v.x, v.y);        ph[1] = packh2(v.z, v.w);
            pl[0] = packh2(v.x - hx, v.y - hy); pl[1] = packh2(v.z - hz, v.w - hw);
        }
    }
    if (tid < 96) {
        float bv = (tid < 32) ? b1[tid] : (tid < 64) ? b2[tid - 32] : b3[tid - 64];
        ((float*)(smem + M2_BI))[tid] = bv;
    }
    __syncthreads();

    const float* sbias = (const float*)(smem + M2_BI);

    // ---- A frags from X (4 k-steps)
    u32 aH[4][4], aL[4][4];
    {
        u32 arow = (u32)(w * 16 + (l & 15)) * XP + (u32)(l >> 4) * 16;
#pragma unroll
        for (int ks = 0; ks < 4; ks++) {
            ldmx4(aH[ks][0], aH[ks][1], aH[ks][2], aH[ks][3], sb + M2_FH + arow + ks * 32);
            ldmx4(aL[ks][0], aL[ks][1], aL[ks][2], aL[ks][3], sb + M2_FL + arow + ks * 32);
        }
    }
    u32 brow = (u32)(l & 15) * PITCH;

    // ---- layer 1: [128x64] @ [64x32] -> h1 frags (2 k-steps for layer 2)
    u32 h1H[2][4], h1L[2][4];
#pragma unroll
    for (int nc = 0; nc < 4; nc++) {
        float cA[4] = {0,0,0,0}, cB[4] = {0,0,0,0}, cC[4] = {0,0,0,0};
#pragma unroll
        for (int ks = 0; ks < 4; ks++) {
            u32 woff = (u32)(ks * 16) * PITCH + (u32)nc * 16 + brow;
            u32 wh0, wh1, wl0, wl1;
            ldmx2t(wh0, wh1, sb + M2_WH + woff);
            ldmx2t(wl0, wl1, sb + M2_WL + woff);
            mma16816(cA[0],cA[1],cA[2],cA[3], aH[ks][0],aH[ks][1],aH[ks][2],aH[ks][3], wh0, wh1);
            mma16816(cB[0],cB[1],cB[2],cB[3], aH[ks][0],aH[ks][1],aH[ks][2],aH[ks][3], wl0, wl1);
            mma16816(cC[0],cC[1],cC[2],cC[3], aL[ks][0],aL[ks][1],aL[ks][2],aL[ks][3], wh0, wh1);
        }
        float b0 = sbias[nc * 8 + 2 * tig], b1v = sbias[nc * 8 + 2 * tig + 1];
        float v0 = fmaxf(cA[0] + cB[0] + cC[0] + b0,  0.f);
        float v1 = fmaxf(cA[1] + cB[1] + cC[1] + b1v, 0.f);
        float v2 = fmaxf(cA[2] + cB[2] + cC[2] + b0,  0.f);
        float v3 = fmaxf(cA[3] + cB[3] + cC[3] + b1v, 0.f);
        u32 h01 = packh2(v0, v1), h23 = packh2(v2, v3);
        float2 f01 = __half22float2(*(__half2*)&h01), f23 = __half22float2(*(__half2*)&h23);
        int ks2 = nc >> 1, pos = (nc & 1) * 2;
        h1H[ks2][pos] = h01; h1H[ks2][pos + 1] = h23;
        h1L[ks2][pos]     = packh2(v0 - f01.x, v1 - f01.y);
        h1L[ks2][pos + 1] = packh2(v2 - f23.x, v3 - f23.y);
    }

    // ---- layer 2: [128x32] @ [32x32]
    u32 h2H[2][4], h2L[2][4];
#pragma unroll
    for (int nc = 0; nc < 4; nc++) {
        float cA[4] = {0,0,0,0}, cB[4] = {0,0,0,0}, cC[4] = {0,0,0,0};
#pragma unroll
        for (int ks = 0; ks < 2; ks++) {
            u32 woff = (u32)(64 + ks * 16) * PITCH + (u32)nc * 16 + brow;
            u32 wh0, wh1, wl0, wl1;
            ldmx2t(wh0, wh1, sb + M2_WH + woff);
            ldmx2t(wl0, wl1, sb + M2_WL + woff);
            mma16816(cA[0],cA[1],cA[2],cA[3], h1H[ks][0],h1H[ks][1],h1H[ks][2],h1H[ks][3], wh0, wh1);
            mma16816(cB[0],cB[1],cB[2],cB[3], h1H[ks][0],h1H[ks][1],h1H[ks][2],h1H[ks][3], wl0, wl1);
            mma16816(cC[0],cC[1],cC[2],cC[3], h1L[ks][0],h1L[ks][1],h1L[ks][2],h1L[ks][3], wh0, wh1);
        }
        float b0 = sbias[32 + nc * 8 + 2 * tig], b1v = sbias[32 + nc * 8 + 2 * tig + 1];
        float v0 = fmaxf(cA[0] + cB[0] + cC[0] + b0,  0.f);
        float v1 = fmaxf(cA[1] + cB[1] + cC[1] + b1v, 0.f);
        float v2 = fmaxf(cA[2] + cB[2] + cC[2] + b0,  0.f);
        float v3 = fmaxf(cA[3] + cB[3] + cC[3] + b1v, 0.f);
        u32 h01 = packh2(v0, v1), h23 = packh2(v2, v3);
        float2 f01 = __half22float2(*(__half2*)&h01), f23 = __half22float2(*(__half2*)&h23);
        int ks2 = nc >> 1, pos = (nc & 1) * 2;
        h2H[ks2][pos] = h01; h2H[ks2][pos + 1] = h23;
        h2L[ks2][pos]     = packh2(v0 - f01.x, v1 - f01.y);
        h2L[ks2][pos + 1] = packh2(v2 - f23.x, v3 - f23.y);
    }

    // ---- layer 3 + epilogue (norms, scaled hi/lo store)
    float nxA = 0.f, nxB = 0.f;
    int rg = row0 + w * 16 + g;
    float sc = isX ? LOG2E : 1.f;
#pragma unroll
    for (int nc = 0; nc < 4; nc++) {
        float cA[4] = {0,0,0,0}, cB[4] = {0,0,0,0}, cC[4] = {0,0,0,0};
#pragma unroll
        for (int ks = 0; ks < 2; ks++) {
            u32 woff = (u32)(96 + ks * 16) * PITCH + (u32)nc * 16 + brow;
            u32 wh0, wh1, wl0, wl1;
            ldmx2t(wh0, wh1, sb + M2_WH + woff);
            ldmx2t(wl0, wl1, sb + M2_WL + woff);
            mma16816(cA[0],cA[1],cA[2],cA[3], h2H[ks][0],h2H[ks][1],h2H[ks][2],h2H[ks][3], wh0, wh1);
            mma16816(cB[0],cB[1],cB[2],cB[3], h2H[ks][0],h2H[ks][1],h2H[ks][2],h2H[ks][3], wl0, wl1);
            mma16816(cC[0],cC[1],cC[2],cC[3], h2L[ks][0],h2L[ks][1],h2L[ks][2],h2L[ks][3], wh0, wh1);
        }
        float b0 = sbias[64 + nc * 8 + 2 * tig], b1v = sbias[64 + nc * 8 + 2 * tig + 1];
        float v0 = fmaxf(cA[0] + cB[0] + cC[0] + b0,  0.f);
        float v1 = fmaxf(cA[1] + cB[1] + cC[1] + b1v, 0.f);
        float v2 = fmaxf(cA[2] + cB[2] + cC[2] + b0,  0.f);
        float v3 = fmaxf(cA[3] + cB[3] + cC[3] + b1v, 0.f);
        nxA += v0 * v0 + v1 * v1;
        nxB += v2 * v2 + v3 * v3;
        float s0 = v0 * sc, s1 = v1 * sc, s2 = v2 * sc, s3 = v3 * sc;
        u32 h01 = packh2(s0, s1), h23 = packh2(s2, s3);
        float2 f01 = __half22float2(*(__half2*)&h01), f23 = __half22float2(*(__half2*)&h23);
        u32 l01 = packh2(s0 - f01.x, s1 - f01.y), l23 = packh2(s2 - f23.x, s3 - f23.y);
        ((u32*)g_Fhi)[rg * 16 + nc * 4 + tig]       = h01;
        ((u32*)g_Fhi)[(rg + 8) * 16 + nc * 4 + tig] = h23;
        ((u32*)g_Flo)[rg * 16 + nc * 4 + tig]       = l01;
        ((u32*)g_Flo)[(rg + 8) * 16 + nc * 4 + tig] = l23;
    }
    nxA += __shfl_xor_sync(0xffffffffu, nxA, 1);
    nxA += __shfl_xor_sync(0xffffffffu, nxA, 2);
    nxB += __shfl_xor_sync(0xffffffffu, nxB, 1);
    nxB += __shfl_xor_sync(0xffffffffu, nxB, 2);
    if (tig == 0) {
        g_Fn[rg]     = -HALF_L2E * nxA;
        g_Fn[rg + 8] = -HALF_L2E * nxB;
    }
}

// ---------------- kernel 2: HMMA flash kernel (consistent denominator) ----------------
__global__ __launch_bounds__(THREADS)
void dist_kernel()
{
    extern __shared__ char smem[];
    u32 sb = smem_u32(smem);
    int tid = threadIdx.x, w = tid >> 5, l = tid & 31;
    int g = l >> 2, tig = l & 3;
    int row0 = blockIdx.x * TTM;
    int m0   = blockIdx.y * (M_ / MSPLIT);

    // ---- preamble: A tile (2 chunks/thread) + tile0 of B/V/cy
    {
#pragma unroll
        for (int q = 0; q < 2; q++) {
            int id = tid + q * THREADS, r = id >> 2, c = id & 3;
            *(uint4*)(smem + S_AHI + r * PITCH + c * 16) = *(const uint4*)(g_Fhi + (size_t)(row0 + r) * H_ + c * 8);
            *(uint4*)(smem + S_ALO + r * PITCH + c * 16) = *(const uint4*)(g_Flo + (size_t)(row0 + r) * H_ + c * 8);
        }
        { int r = tid >> 2, c = tid & 3;
          *(uint4*)(smem + S_B + r * PITCH + c * 16)         = *(const uint4*)(g_Fhi + (size_t)(N_ + m0 + r) * H_ + c * 8);
          *(uint4*)(smem + S_B + 10240 + r * PITCH + c * 16) = *(const uint4*)(g_Flo + (size_t)(N_ + m0 + r) * H_ + c * 8); }
        if (tid < 128)      *(uint4*)(smem + S_V + tid * 16)            = *(const uint4*)(g_Vhi + (size_t)(m0 + tid) * T_);
        else if (tid < 256) *(uint4*)(smem + S_V + 2048 + (tid-128)*16) = *(const uint4*)(g_Vlo + (size_t)(m0 + tid - 128) * T_);
        else if (tid < 384) ((float*)(smem + S_CY))[tid - 256] = g_Fn[N_ + m0 + tid - 256];
    }
    __syncthreads();

    // ---- persistent A fragments
    u32 aH0[4], aH1[4], aL0[4], aL1[4];
    {
        u32 arow = (u32)(w * 16 + (l & 15)) * PITCH + (u32)(l >> 4) * 16;
        ldmx4(aH0[0], aH0[1], aH0[2], aH0[3], sb + S_AHI + arow);
        ldmx4(aH1[0], aH1[1], aH1[2], aH1[3], sb + S_AHI + arow + 32);
        ldmx4(aL0[0], aL0[1], aL0[2], aL0[3], sb + S_ALO + arow);
        ldmx4(aL1[0], aL1[1], aL1[2], aL1[3], sb + S_ALO + arow + 32);
    }

    float cx0 = g_Fn[row0 + w * 16 + g];
    float cx1 = g_Fn[row0 + w * 16 + g + 8];

    float oA0 = 0.f, oA1 = 0.f, oA2 = 0.f, oA3 = 0.f;   // P@Vhi chain
    float oB0 = 0.f, oB1 = 0.f, oB2 = 0.f, oB3 = 0.f;   // P@Vlo chain
    float s0 = 0.f, s1 = 0.f;                           // sums of ROUNDED kv

    u32 bArow = (u32)(l & 7) * PITCH + (u32)(l >> 3) * 16;
    u32 vArow = (u32)(l & 15) * 16;

#pragma unroll 1
    for (int i = 0; i < TILES; i++) {
        uint4 nbh, nbl, nv; float ncy = 0.f;
        bool pf = (i + 1 < TILES);
        if (pf) {
            int mb = m0 + (i + 1) * TTN;
            { int r = tid >> 2, c = tid & 3;
              nbh = *(const uint4*)(g_Fhi + (size_t)(N_ + mb + r) * H_ + c * 8);
              nbl = *(const uint4*)(g_Flo + (size_t)(N_ + mb + r) * H_ + c * 8); }
            if (tid < 128)      nv  = *(const uint4*)(g_Vhi + (size_t)(mb + tid) * T_);
            else if (tid < 256) nv  = *(const uint4*)(g_Vlo + (size_t)(mb + tid - 128) * T_);
            else if (tid < 384) ncy = g_Fn[N_ + mb + tid - 256];
        }

        int ib = i & 1;
        u32 Bhi = sb + S_B + ib * 20480, Blo = Bhi + 10240;
        u32 Vhi = sb + S_V + ib * 4096,  Vlo = Vhi + 2048;
        const float* cyb = (const float*)(smem + S_CY + ib * 512);

#pragma unroll 1
        for (int s = 0; s < 8; s++) {
            u32 aP[4];
#pragma unroll
            for (int hhalf = 0; hhalf < 2; hhalf++) {
                int nc = 2 * s + hhalf;
                u32 bh[4], bl[4];
                ldmx4(bh[0], bh[1], bh[2], bh[3], Bhi + (u32)nc * (8 * PITCH) + bArow);
                ldmx4(bl[0], bl[1], bl[2], bl[3], Blo + (u32)nc * (8 * PITCH) + bArow);

                // 3 independent 2-MMA chains
                float cA0 = 0.f, cA1 = 0.f, cA2 = 0.f, cA3 = 0.f;
                float cB0 = 0.f, cB1 = 0.f, cB2 = 0.f, cB3 = 0.f;
                float cC0 = 0.f, cC1 = 0.f, cC2 = 0.f, cC3 = 0.f;
                mma16816(cA0, cA1, cA2, cA3, aH0[0], aH0[1], aH0[2], aH0[3], bh[0], bh[1]);
                mma16816(cB0, cB1, cB2, cB3, aH0[0], aH0[1], aH0[2], aH0[3], bl[0], bl[1]);
                mma16816(cC0, cC1, cC2, cC3, aL0[0], aL0[1], aL0[2], aL0[3], bh[0], bh[1]);
                mma16816(cA0, cA1, cA2, cA3, aH1[0], aH1[1], aH1[2], aH1[3], bh[2], bh[3]);
                mma16816(cB0, cB1, cB2, cB3, aH1[0], aH1[1], aH1[2], aH1[3], bl[2], bl[3]);
                mma16816(cC0, cC1, cC2, cC3, aL1[0], aL1[1], aL1[2], aL1[3], bh[2], bh[3]);
                float c0 = cA0 + cB0 + cC0, c1 = cA1 + cB1 + cC1;
                float c2 = cA2 + cB2 + cC2, c3 = cA3 + cB3 + cC3;

                float2 cy = *(const float2*)(cyb + nc * 8 + 2 * tig);
                float k0 = ex2f(fminf(c0 + (cx0 + cy.x), 0.f));
                float k1 = ex2f(fminf(c1 + (cx0 + cy.y), 0.f));
                float k2 = ex2f(fminf(c2 + (cx1 + cy.x), 0.f));
                float k3 = ex2f(fminf(c3 + (cx1 + cy.y), 0.f));

                u32 h01 = packh2(k0, k1), h23 = packh2(k2, k3);
                // denominator sums the ROUNDED kv -> consistent with numerator
                float2 f01 = __half22float2(*(__half2*)&h01);
                float2 f23 = __half22float2(*(__half2*)&h23);
                s0 += f01.x + f01.y;
                s1 += f23.x + f23.y;
                aP[2 * hhalf]     = h01;
                aP[2 * hhalf + 1] = h23;
            }

            u32 vh[2], vl[2];
            ldmx2t(vh[0], vh[1], Vhi + (u32)s * 256 + vArow);
            ldmx2t(vl[0], vl[1], Vlo + (u32)s * 256 + vArow);
            mma16816(oA0, oA1, oA2, oA3, aP[0], aP[1], aP[2], aP[3], vh[0], vh[1]);
            mma16816(oB0, oB1, oB2, oB3, aP[0], aP[1], aP[2], aP[3], vl[0], vl[1]);
        }

        if (pf) {
            int ib2 = (i + 1) & 1;
            { int r = tid >> 2, c = tid & 3;
              *(uint4*)(smem + S_B + ib2 * 20480 + r * PITCH + c * 16)         = nbh;
              *(uint4*)(smem + S_B + ib2 * 20480 + 10240 + r * PITCH + c * 16) = nbl; }
            if (tid < 128)      *(uint4*)(smem + S_V + ib2 * 4096 + tid * 16)              = nv;
            else if (tid < 256) *(uint4*)(smem + S_V + ib2 * 4096 + 2048 + (tid-128) * 16) = nv;
            else if (tid < 384) ((float*)(smem + S_CY + ib2 * 512))[tid - 256] = ncy;
        }
        __syncthreads();
    }

    float o0 = oA0 + oB0, o1 = oA1 + oB1, o2 = oA2 + oB2, o3 = oA3 + oB3;

    s0 += __shfl_xor_sync(0xffffffffu, s0, 1);
    s0 += __shfl_xor_sync(0xffffffffu, s0, 2);
    s1 += __shfl_xor_sync(0xffffffffu, s1, 1);
    s1 += __shfl_xor_sync(0xffffffffu, s1, 2);

    int ra = row0 + w * 16 + g;
    int rb = ra + 8;
    int by = blockIdx.y;
    g_part[IDXP(by, 2 * tig,     ra)] = o0;
    g_part[IDXP(by, 2 * tig + 1, ra)] = o1;
    g_part[IDXP(by, 2 * tig,     rb)] = o2;
    g_part[IDXP(by, 2 * tig + 1, rb)] = o3;
    if (tig == 0) { g_part[IDXP(by, T_, ra)] = s0; g_part[IDXP(by, T_, rb)] = s1; }
}

// ---------------- kernel 3: combine partials, normalize (coalesced) ----------------
__global__ __launch_bounds__(256)
void reduce_kernel(float* __restrict__ out)
{
    int row = blockIdx.x * 256 + threadIdx.x;   // N_ rows
    float sk = 0.f;
#pragma unroll
    for (int c = 0; c < MSPLIT; c++) sk += g_part[IDXP(c, T_, row)];
    float inv = 1.f / sk;
    float o[T_];
#pragma unroll
    for (int t = 0; t < T_; t++) {
        float st = 0.f;
#pragma unroll
        for (int c = 0; c < MSPLIT; c++) st += g_part[IDXP(c, t, row)];
        o[t] = st * inv;
    }
    float4* dst = (float4*)(out + (size_t)row * T_);
    dst[0] = make_float4(o[0], o[1], o[2], o[3]);
    dst[1] = make_float4(o[4], o[5], o[6], o[7]);
}

// ---------------- launch ----------------
extern "C" void kernel_launch(void* const* d_in, const int* in_sizes, int n_in,
                              void* d_out, int out_size)
{
    (void)in_sizes; (void)n_in; (void)out_size;
    const float* X  = (const float*)d_in[0];
    const float* Y  = (const float*)d_in[1];
    const float* Yt = (const float*)d_in[2];
    const float* W1 = (const float*)d_in[3];
    const float* b1 = (const float*)d_in[4];
    const float* W2 = (const float*)d_in[5];
    const float* b2 = (const float*)d_in[6];
    const float* W3 = (const float*)d_in[7];
    const float* b3 = (const float*)d_in[8];
    float* out = (float*)d_out;

    cudaFuncSetAttribute(mlp2_kernel, cudaFuncAttributeMaxDynamicSharedMemorySize, M2_TOTAL);
    cudaFuncSetAttribute(dist_kernel, cudaFuncAttributeMaxDynamicSharedMemorySize, SMEM_TOTAL);

    mlp2_kernel<<<MLP2BLKS + (M_ * T_) / 256, 256, M2_TOTAL>>>(X, Y, Yt, W1, b1, W2, b2, W3, b3);
    dist_kernel<<<dim3(N_ / TTM, MSPLIT), THREADS, SMEM_TOTAL>>>();
    reduce_kernel<<<N_ / 256, 256>>>(out);
}